// round 1
// baseline (speedup 1.0000x reference)
#include <cuda_runtime.h>
#include <cstdint>

#define NB   16
#define CIN  512
#define COUT 512
#define HIN  32
#define XUS  66
#define RES  64

// Scratch (device globals — no allocation allowed)
__device__ float g_styles[NB * CIN];
__device__ float g_dcoef[NB * COUT];
__device__ float g_wsq[COUT * CIN];
__device__ float g_wt[CIN * 9 * COUT];                 // flipped + transposed weights [ci][k][co]
__device__ float g_xm[(size_t)NB * CIN * XUS * XUS];   // modulated upsampled input, ~143 MB

// ---------------------------------------------------------------------------
// styles[b,c] = dot(w[b,:], affine_weight[c,:]) / sqrt(512) + affine_bias[c]
// ---------------------------------------------------------------------------
__global__ void styles_kernel(const float* __restrict__ w,
                              const float* __restrict__ aw,
                              const float* __restrict__ ab) {
    __shared__ float sw[CIN];
    int b = blockIdx.y;
    int c = blockIdx.x * 128 + threadIdx.x;
    for (int i = threadIdx.x; i < CIN; i += 128) sw[i] = w[b * CIN + i];
    __syncthreads();
    const float* row = aw + (size_t)c * CIN;
    float s = 0.f;
#pragma unroll 4
    for (int k = 0; k < CIN; k++) s += sw[k] * row[k];
    g_styles[b * CIN + c] = s * 0.044194173824159216f + ab[c];
}

// ---------------------------------------------------------------------------
// wsq[co,ci] = sum_k weight[co,ci,k]^2
// ---------------------------------------------------------------------------
__global__ void wsq_kernel(const float* __restrict__ weight) {
    int idx = blockIdx.x * 256 + threadIdx.x;   // < COUT*CIN
    const float* p = weight + (size_t)idx * 9;
    float s = 0.f;
#pragma unroll
    for (int k = 0; k < 9; k++) { float v = p[k]; s += v * v; }
    g_wsq[idx] = s;
}

// ---------------------------------------------------------------------------
// wt[ci][k][co] = weight[co][ci][8-k]   (flip 3x3 for true convolution)
// ---------------------------------------------------------------------------
__global__ void wt_kernel(const float* __restrict__ weight) {
    int idx = blockIdx.x * 256 + threadIdx.x;   // < CIN*9*COUT
    int co = idx & 511;
    int k  = (idx >> 9) % 9;
    int ci = idx / (9 * 512);
    g_wt[idx] = weight[(size_t)co * (CIN * 9) + ci * 9 + (8 - k)];
}

// ---------------------------------------------------------------------------
// dcoef[b,co] = rsqrt(sum_ci wsq[co,ci]*styles[b,ci]^2 + 1e-8)
// ---------------------------------------------------------------------------
__global__ void dcoef_kernel() {
    __shared__ float s2[CIN];
    int b = blockIdx.y;
    int c = blockIdx.x * 128 + threadIdx.x;
    for (int i = threadIdx.x; i < CIN; i += 128) {
        float s = g_styles[b * CIN + i];
        s2[i] = s * s;
    }
    __syncthreads();
    const float* row = g_wsq + (size_t)c * CIN;
    float s = 0.f;
#pragma unroll 4
    for (int k = 0; k < CIN; k++) s += row[k] * s2[k];
    g_dcoef[b * COUT + c] = rsqrtf(s + 1e-8f);
}

// ---------------------------------------------------------------------------
// upfirdn2d up=2 (separable 4-tap [.25 .75 .75 .25] per dim) fused with
// input-side style modulation: xm[b,ci] = upfirdn(x[b,ci]) * styles[b,ci]
// ---------------------------------------------------------------------------
__global__ void up_kernel(const float* __restrict__ x) {
    __shared__ float sx[HIN * HIN];
    int bc = blockIdx.x;                       // b*CIN + ci
    const float* xp = x + (size_t)bc * HIN * HIN;
    for (int i = threadIdx.x; i < HIN * HIN; i += 256) sx[i] = xp[i];
    __syncthreads();
    float st = g_styles[bc];
    float* op = g_xm + (size_t)bc * XUS * XUS;
    for (int p = threadIdx.x; p < XUS * XUS; p += 256) {
        int i = p / XUS, j = p % XUS;
        int i0, i1; float wv0, wv1;
        if ((i & 1) == 0) { i0 = (i - 2) >> 1; wv0 = 0.75f; i1 = i >> 1;       wv1 = 0.25f; }
        else              { i0 = (i - 3) >> 1; wv0 = 0.25f; i1 = (i - 1) >> 1; wv1 = 0.75f; }
        if (i0 < 0 || i0 >= HIN) { i0 = 0; wv0 = 0.f; }
        if (i1 < 0 || i1 >= HIN) { i1 = 0; wv1 = 0.f; }
        int j0, j1; float wh0, wh1;
        if ((j & 1) == 0) { j0 = (j - 2) >> 1; wh0 = 0.75f; j1 = j >> 1;       wh1 = 0.25f; }
        else              { j0 = (j - 3) >> 1; wh0 = 0.25f; j1 = (j - 1) >> 1; wh1 = 0.75f; }
        if (j0 < 0 || j0 >= HIN) { j0 = 0; wh0 = 0.f; }
        if (j1 < 0 || j1 >= HIN) { j1 = 0; wh1 = 0.f; }
        float v = wv0 * (wh0 * sx[i0 * HIN + j0] + wh1 * sx[i0 * HIN + j1])
                + wv1 * (wh0 * sx[i1 * HIN + j0] + wh1 * sx[i1 * HIN + j1]);
        op[p] = v * st;
    }
}

// ---------------------------------------------------------------------------
// Main conv as implicit GEMM, fp32x2 packed FMA (2x scalar-FFMA throughput).
// Block tile: 128 pixels (8 rows x 16 cols) x 128 cout. Thread: 8 px x 8 co.
// K loop: Cin in chunks of 8, 3x3 taps unrolled.
// Epilogue: *dcoef + noise*strength + bias -> leaky_relu * sqrt(2).
// ---------------------------------------------------------------------------
__device__ __forceinline__ unsigned long long pack2(float a) {
    unsigned int u = __float_as_uint(a);
    unsigned long long r;
    asm("mov.b64 %0, {%1, %1};" : "=l"(r) : "r"(u));
    return r;
}
__device__ __forceinline__ void fma2(unsigned long long& acc,
                                     unsigned long long a, unsigned long long b) {
    asm("fma.rn.f32x2 %0, %1, %2, %0;" : "+l"(acc) : "l"(a), "l"(b));
}

__global__ __launch_bounds__(256, 2) void conv_kernel(
    const float* __restrict__ bias, const float* __restrict__ noise,
    const float* __restrict__ nsp, float* __restrict__ out) {
    __shared__ float sA[8][10][18];                       // 8 ci x (8+2)x(16+2) patch
    __shared__ __align__(16) float sB[8][9][128];         // 8 ci x 9 taps x 128 co

    int t = threadIdx.x;
    int tile_w = blockIdx.x & 3, tile_h = blockIdx.x >> 2;
    int co0 = blockIdx.y * 128;
    int b = blockIdx.z;
    int oh0 = tile_h * 8, ow0 = tile_w * 16;
    int tx = t & 15, ty = t >> 4;
    int pr0 = (ty >> 2) * 2, pc0 = (ty & 3) * 4;          // thread's 2 rows x 4 cols

    unsigned long long acc[2][4][4];                      // [pr][pc][co-pair]
#pragma unroll
    for (int a = 0; a < 2; a++)
#pragma unroll
        for (int p = 0; p < 4; p++)
#pragma unroll
            for (int c = 0; c < 4; c++) acc[a][p][c] = 0ull;

    const float* xmb = g_xm + (size_t)b * CIN * XUS * XUS;

    for (int ci0 = 0; ci0 < CIN; ci0 += 8) {
        __syncthreads();
        // fill sA: 8*10*18 = 1440 floats
        for (int i = t; i < 8 * 180; i += 256) {
            int ci = i / 180, rem = i % 180, r = rem / 18, c = rem % 18;
            sA[ci][r][c] = xmb[(size_t)(ci0 + ci) * (XUS * XUS) + (oh0 + r) * XUS + (ow0 + c)];
        }
        // fill sB: 8*9*128 floats via float4, coalesced from g_wt[ci][k][co]
        float4* sB4 = (float4*)sB;
        for (int i = t; i < 8 * 9 * 32; i += 256) {
            int ci = i / 288, rem = i % 288, k = rem >> 5, cv = rem & 31;
            sB4[i] = *(const float4*)(g_wt + ((size_t)(ci0 + ci) * 9 + k) * COUT + co0 + cv * 4);
        }
        __syncthreads();

#pragma unroll 1
        for (int ci = 0; ci < 8; ci++) {
#pragma unroll
            for (int kh = 0; kh < 3; kh++) {
#pragma unroll
                for (int kw = 0; kw < 3; kw++) {
                    unsigned long long a2[2][4];
#pragma unroll
                    for (int pr = 0; pr < 2; pr++)
#pragma unroll
                        for (int pc = 0; pc < 4; pc++)
                            a2[pr][pc] = pack2(sA[ci][pr0 + pr + kh][pc0 + pc + kw]);
                    const unsigned long long* bp =
                        (const unsigned long long*)&sB[ci][kh * 3 + kw][tx * 8];
                    unsigned long long b0 = bp[0], b1 = bp[1], b2v = bp[2], b3 = bp[3];
#pragma unroll
                    for (int pr = 0; pr < 2; pr++)
#pragma unroll
                        for (int pc = 0; pc < 4; pc++) {
                            fma2(acc[pr][pc][0], a2[pr][pc], b0);
                            fma2(acc[pr][pc][1], a2[pr][pc], b1);
                            fma2(acc[pr][pc][2], a2[pr][pc], b2v);
                            fma2(acc[pr][pc][3], a2[pr][pc], b3);
                        }
                }
            }
        }
    }

    // Epilogue
    float ns = nsp[0];
    float dc[8], bs[8];
#pragma unroll
    for (int j = 0; j < 8; j++) {
        int co = co0 + tx * 8 + j;
        dc[j] = g_dcoef[b * COUT + co];
        bs[j] = bias[co];
    }
#pragma unroll
    for (int pr = 0; pr < 2; pr++) {
        int oh = oh0 + pr0 + pr;
#pragma unroll
        for (int j = 0; j < 8; j++) {
            int co = co0 + tx * 8 + j;
            float4 v;
            float* vp = (float*)&v;
#pragma unroll
            for (int pc = 0; pc < 4; pc++) {
                unsigned long long u = acc[pr][pc][j >> 1];
                float f = (j & 1) ? __uint_as_float((unsigned int)(u >> 32))
                                  : __uint_as_float((unsigned int)u);
                int ow = ow0 + pc0 + pc;
                float val = f * dc[j] + noise[oh * RES + ow] * ns + bs[j];
                val = (val > 0.f) ? val : 0.2f * val;
                vp[pc] = val * 1.4142135623730951f;
            }
            *(float4*)(out + (((size_t)b * COUT + co) * RES + oh) * RES + ow0 + pc0) = v;
        }
    }
}

// ---------------------------------------------------------------------------
extern "C" void kernel_launch(void* const* d_in, const int* in_sizes, int n_in,
                              void* d_out, int out_size) {
    const float* x      = (const float*)d_in[0];
    const float* w      = (const float*)d_in[1];
    const float* aw     = (const float*)d_in[2];
    const float* ab     = (const float*)d_in[3];
    const float* weight = (const float*)d_in[4];
    const float* bias   = (const float*)d_in[5];
    const float* noise  = (const float*)d_in[6];
    const float* nstr   = (const float*)d_in[7];
    float* out = (float*)d_out;

    styles_kernel<<<dim3(4, NB), 128>>>(w, aw, ab);
    wsq_kernel<<<COUT * CIN / 256, 256>>>(weight);
    wt_kernel<<<CIN * 9 * COUT / 256, 256>>>(weight);
    dcoef_kernel<<<dim3(4, NB), 128>>>();
    up_kernel<<<NB * CIN, 256>>>(x);
    conv_kernel<<<dim3(32, 4, NB), 256>>>(bias, noise, nstr, out);
}

// round 4
// speedup vs baseline: 1.8309x; 1.8309x over previous
#include <cuda_runtime.h>
#include <cstdint>

#define NB   16
#define CIN  512
#define COUT 512
#define HIN  32
#define XUS  66
#define RES  64

// Scratch (device globals — no allocation allowed)
__device__ float g_styles[NB * CIN];
__device__ float g_dcoef[NB * COUT];
__device__ float g_wsq[COUT * CIN];
// wt2[cc][tap][co][cl] : cc = ci/8 chunk, tap = flipped 3x3 index, cl = ci%8
__device__ float g_wt2[64 * 9 * 512 * 8];
__device__ float g_xm[(size_t)NB * CIN * XUS * XUS];   // modulated upsampled input (tf32-rounded)

// ---------------------------------------------------------------------------
__device__ __forceinline__ float rna_tf32(float x) {
    unsigned u;
    asm("cvt.rna.tf32.f32 %0, %1;" : "=r"(u) : "f"(x));
    return __uint_as_float(u);
}

// ---------------------------------------------------------------------------
// styles[b,c] = dot(w[b,:], affine_weight[c,:]) / sqrt(512) + affine_bias[c]
// ---------------------------------------------------------------------------
__global__ void styles_kernel(const float* __restrict__ w,
                              const float* __restrict__ aw,
                              const float* __restrict__ ab) {
    __shared__ float sw[CIN];
    int b = blockIdx.y;
    int c = blockIdx.x * 128 + threadIdx.x;
    for (int i = threadIdx.x; i < CIN; i += 128) sw[i] = w[b * CIN + i];
    __syncthreads();
    const float* row = aw + (size_t)c * CIN;
    float s = 0.f;
#pragma unroll 4
    for (int k = 0; k < CIN; k++) s += sw[k] * row[k];
    g_styles[b * CIN + c] = s * 0.044194173824159216f + ab[c];
}

// ---------------------------------------------------------------------------
// wsq[co,ci] = sum_k weight[co,ci,k]^2   (exact fp32, for demodulation)
// ---------------------------------------------------------------------------
__global__ void wsq_kernel(const float* __restrict__ weight) {
    int idx = blockIdx.x * 256 + threadIdx.x;   // < COUT*CIN
    const float* p = weight + (size_t)idx * 9;
    float s = 0.f;
#pragma unroll
    for (int k = 0; k < 9; k++) { float v = p[k]; s += v * v; }
    g_wsq[idx] = s;
}

// ---------------------------------------------------------------------------
// wt2[cc][tap][co][cl] = rna_tf32( weight[co][cc*8+cl][8-tap] )   (3x3 flip)
// ---------------------------------------------------------------------------
__global__ void wt2_kernel(const float* __restrict__ weight) {
    int idx = blockIdx.x * 256 + threadIdx.x;   // < 64*9*512*8
    int cl  = idx & 7;
    int co  = (idx >> 3) & 511;
    int tap = (idx >> 12) % 9;
    int cc  = idx / (9 * 4096);
    int ci  = cc * 8 + cl;
    g_wt2[idx] = rna_tf32(weight[(size_t)co * (CIN * 9) + ci * 9 + (8 - tap)]);
}

// ---------------------------------------------------------------------------
// dcoef[b,co] = rsqrt(sum_ci wsq[co,ci]*styles[b,ci]^2 + 1e-8)
// ---------------------------------------------------------------------------
__global__ void dcoef_kernel() {
    __shared__ float s2[CIN];
    int b = blockIdx.y;
    int c = blockIdx.x * 128 + threadIdx.x;
    for (int i = threadIdx.x; i < CIN; i += 128) {
        float s = g_styles[b * CIN + i];
        s2[i] = s * s;
    }
    __syncthreads();
    const float* row = g_wsq + (size_t)c * CIN;
    float s = 0.f;
#pragma unroll 4
    for (int k = 0; k < CIN; k++) s += row[k] * s2[k];
    g_dcoef[b * COUT + c] = rsqrtf(s + 1e-8f);
}

// ---------------------------------------------------------------------------
// upfirdn2d up=2 fused with input-side style modulation, output tf32-rounded
// ---------------------------------------------------------------------------
__global__ void up_kernel(const float* __restrict__ x) {
    __shared__ float sx[HIN * HIN];
    int bc = blockIdx.x;                       // b*CIN + ci
    const float* xp = x + (size_t)bc * HIN * HIN;
    for (int i = threadIdx.x; i < HIN * HIN; i += 256) sx[i] = xp[i];
    __syncthreads();
    float st = g_styles[bc];
    float* op = g_xm + (size_t)bc * XUS * XUS;
    for (int p = threadIdx.x; p < XUS * XUS; p += 256) {
        int i = p / XUS, j = p % XUS;
        int i0, i1; float wv0, wv1;
        if ((i & 1) == 0) { i0 = (i - 2) >> 1; wv0 = 0.75f; i1 = i >> 1;       wv1 = 0.25f; }
        else              { i0 = (i - 3) >> 1; wv0 = 0.25f; i1 = (i - 1) >> 1; wv1 = 0.75f; }
        if (i0 < 0 || i0 >= HIN) { i0 = 0; wv0 = 0.f; }
        if (i1 < 0 || i1 >= HIN) { i1 = 0; wv1 = 0.f; }
        int j0, j1; float wh0, wh1;
        if ((j & 1) == 0) { j0 = (j - 2) >> 1; wh0 = 0.75f; j1 = j >> 1;       wh1 = 0.25f; }
        else              { j0 = (j - 3) >> 1; wh0 = 0.25f; j1 = (j - 1) >> 1; wh1 = 0.75f; }
        if (j0 < 0 || j0 >= HIN) { j0 = 0; wh0 = 0.f; }
        if (j1 < 0 || j1 >= HIN) { j1 = 0; wh1 = 0.f; }
        float v = wv0 * (wh0 * sx[i0 * HIN + j0] + wh1 * sx[i0 * HIN + j1])
                + wv1 * (wh0 * sx[i1 * HIN + j0] + wh1 * sx[i1 * HIN + j1]);
        op[p] = rna_tf32(v * st);
    }
}

// ---------------------------------------------------------------------------
// Main conv: implicit GEMM on tf32 tensor cores (mma.sync m16n8k8).
// Block: 256 px (16x16) x 128 co, 512 threads = 16 warps (8 M-warps x 2 N).
// Warp tile: 32 px (2 x m16) x 64 co (8 x n8).  K = 512 ci (chunks of 8) x 9 taps.
// ci-pairs packed innermost in smem so all fragment loads are conflict-free LDS.64.
// ---------------------------------------------------------------------------
__device__ __forceinline__ void mma_tf32(float* d, float2 alo, float2 ahi, float2 bf) {
    asm volatile(
        "mma.sync.aligned.m16n8k8.row.col.f32.tf32.tf32.f32 "
        "{%0,%1,%2,%3}, {%4,%5,%6,%7}, {%8,%9}, {%0,%1,%2,%3};\n"
        : "+f"(d[0]), "+f"(d[1]), "+f"(d[2]), "+f"(d[3])
        : "r"(__float_as_uint(alo.x)), "r"(__float_as_uint(ahi.x)),
          "r"(__float_as_uint(alo.y)), "r"(__float_as_uint(ahi.y)),
          "r"(__float_as_uint(bf.x)),  "r"(__float_as_uint(bf.y)));
}

__global__ __launch_bounds__(512, 1) void conv_kernel(
    const float* __restrict__ bias, const float* __restrict__ noise,
    const float* __restrict__ nsp, float* __restrict__ out) {
    __shared__ float sA[18][18][8];        // [row][col][ci]  10368 B
    __shared__ float sB[9][128][8];        // [tap][co_local][ci]  36864 B

    const int t    = threadIdx.x;
    const int lane = t & 31;
    const int wid  = t >> 5;
    const int wm   = wid & 7;              // M-warp: image rows wm*2, wm*2+1
    const int wn   = wid >> 3;             // N-warp: co offset wn*64
    const int g    = lane >> 2;            // 0..7
    const int tg   = lane & 3;             // 0..3  (ci-pair = 2tg, 2tg+1)

    const int tile_h = blockIdx.x >> 2, tile_w = blockIdx.x & 3;
    const int oh0 = tile_h * 16, ow0 = tile_w * 16;
    const int co0 = blockIdx.y * 128;
    const int b   = blockIdx.z;

    float acc[2][8][4];
#pragma unroll
    for (int mi = 0; mi < 2; mi++)
#pragma unroll
        for (int nt = 0; nt < 8; nt++)
#pragma unroll
            for (int r = 0; r < 4; r++) acc[mi][nt][r] = 0.f;

    const float* xmb = g_xm + (size_t)b * CIN * XUS * XUS;
    const float2 (*sA2)[18][4] = (const float2(*)[18][4])sA;
    const float2 (*sB2)[128][4] = (const float2(*)[128][4])sB;
    float4* sB4 = (float4*)sB;

    for (int cc = 0; cc < 64; cc++) {
        __syncthreads();
        // fill sA: 18x18 patch x 8 ci  (2592 floats); ci innermost across lanes
        // -> consecutive STS words, conflict-free
        const int ci0 = cc * 8;
#pragma unroll 1
        for (int i = t; i < 18 * 18 * 8; i += 512) {
            int ci = i & 7;
            int rc = i >> 3;
            int r = rc / 18, c = rc - r * 18;
            sA[r][c][ci] = xmb[(size_t)(ci0 + ci) * (XUS * XUS) + (oh0 + r) * XUS + (ow0 + c)];
        }
        // fill sB: 9 taps x 128 co x 8 ci via float4, fully coalesced copy
#pragma unroll 1
        for (int i = t; i < 9 * 128 * 2; i += 512) {
            int tap = i >> 8, j = i & 255;
            sB4[i] = *((const float4*)(g_wt2 + (((size_t)cc * 9 + tap) * 512 + co0) * 8) + j);
        }
        __syncthreads();

#pragma unroll
        for (int kh = 0; kh < 3; kh++) {
            float2 ar[2][6];
#pragma unroll
            for (int mi = 0; mi < 2; mi++) {
                int r = wm * 2 + mi + kh;
#pragma unroll
                for (int q = 0; q < 3; q++) {
                    ar[mi][q]     = sA2[r][g + q][tg];
                    ar[mi][3 + q] = sA2[r][g + 8 + q][tg];
                }
            }
#pragma unroll
            for (int kw = 0; kw < 3; kw++) {
                int tap = kh * 3 + kw;
#pragma unroll
                for (int nt = 0; nt < 8; nt++) {
                    float2 bf = sB2[tap][wn * 64 + nt * 8 + g][tg];
#pragma unroll
                    for (int mi = 0; mi < 2; mi++)
                        mma_tf32(acc[mi][nt], ar[mi][kw], ar[mi][3 + kw], bf);
                }
            }
        }
    }

    // Epilogue: *dcoef + noise*strength + bias -> leaky_relu * sqrt(2)
    const float ns = nsp[0];
    float dcv[8][2], bsv[8][2];
#pragma unroll
    for (int nt = 0; nt < 8; nt++) {
        int co = co0 + wn * 64 + nt * 8 + 2 * tg;
        dcv[nt][0] = g_dcoef[b * COUT + co];
        dcv[nt][1] = g_dcoef[b * COUT + co + 1];
        bsv[nt][0] = bias[co];
        bsv[nt][1] = bias[co + 1];
    }
#pragma unroll
    for (int mi = 0; mi < 2; mi++) {
        int oh = oh0 + wm * 2 + mi;
        float nz0 = noise[oh * RES + ow0 + g] * ns;
        float nz1 = noise[oh * RES + ow0 + g + 8] * ns;
#pragma unroll
        for (int nt = 0; nt < 8; nt++) {
            int co = co0 + wn * 64 + nt * 8 + 2 * tg;
            float v0 = acc[mi][nt][0] * dcv[nt][0] + nz0 + bsv[nt][0];
            float v1 = acc[mi][nt][1] * dcv[nt][1] + nz0 + bsv[nt][1];
            float v2 = acc[mi][nt][2] * dcv[nt][0] + nz1 + bsv[nt][0];
            float v3 = acc[mi][nt][3] * dcv[nt][1] + nz1 + bsv[nt][1];
            v0 = ((v0 > 0.f) ? v0 : 0.2f * v0) * 1.4142135623730951f;
            v1 = ((v1 > 0.f) ? v1 : 0.2f * v1) * 1.4142135623730951f;
            v2 = ((v2 > 0.f) ? v2 : 0.2f * v2) * 1.4142135623730951f;
            v3 = ((v3 > 0.f) ? v3 : 0.2f * v3) * 1.4142135623730951f;
            size_t p0 = (((size_t)b * COUT + co) * RES + oh) * RES + ow0;
            size_t p1 = (((size_t)b * COUT + co + 1) * RES + oh) * RES + ow0;
            out[p0 + g]     = v0;
            out[p1 + g]     = v1;
            out[p0 + g + 8] = v2;
            out[p1 + g + 8] = v3;
        }
    }
}

// ---------------------------------------------------------------------------
extern "C" void kernel_launch(void* const* d_in, const int* in_sizes, int n_in,
                              void* d_out, int out_size) {
    const float* x      = (const float*)d_in[0];
    const float* w      = (const float*)d_in[1];
    const float* aw     = (const float*)d_in[2];
    const float* ab     = (const float*)d_in[3];
    const float* weight = (const float*)d_in[4];
    const float* bias   = (const float*)d_in[5];
    const float* noise  = (const float*)d_in[6];
    const float* nstr   = (const float*)d_in[7];
    float* out = (float*)d_out;

    styles_kernel<<<dim3(4, NB), 128>>>(w, aw, ab);
    wsq_kernel<<<COUT * CIN / 256, 256>>>(weight);
    wt2_kernel<<<64 * 9 * 512 * 8 / 256, 256>>>(weight);
    dcoef_kernel<<<dim3(4, NB), 128>>>();
    up_kernel<<<NB * CIN, 256>>>(x);
    conv_kernel<<<dim3(16, 4, NB), 512>>>(bias, noise, nstr, out);
}

// round 8
// speedup vs baseline: 5.0445x; 2.7552x over previous
#include <cuda_runtime.h>
#include <cuda_fp16.h>
#include <cstdint>

#define NB   16
#define CIN  512
#define COUT 512
#define HIN  32
#define XUS  66
#define RES  64
#define NC2  (CIN / 2)          // 256 ci-pairs
#define NCC  32                 // ci chunks of 16

// Scratch (device globals — no allocation allowed)
__device__ float g_styles[NB * CIN];
__device__ float g_dcoef[NB * COUT];
__device__ float g_wsq[COUT * CIN];
// wt3[cc][tap][co][slot]: fp16, slot s -> ci = cc*16 + perm(s)  (3x3 flipped)
__device__ __half g_wt3[NCC * 9 * COUT * 16];
// xm2[b][c2][pix]: __half2 of ci-pair (2*c2, 2*c2+1), modulated+upsampled
__device__ unsigned g_xm2[(size_t)NB * NC2 * XUS * XUS];

// ---------------------------------------------------------------------------
// styles[b,c] = dot(w[b,:], affine_weight[c,:]) / sqrt(512) + affine_bias[c]
// ---------------------------------------------------------------------------
__global__ void styles_kernel(const float* __restrict__ w,
                              const float* __restrict__ aw,
                              const float* __restrict__ ab) {
    __shared__ float sw[CIN];
    int b = blockIdx.y;
    int c = blockIdx.x * 128 + threadIdx.x;
    for (int i = threadIdx.x; i < CIN; i += 128) sw[i] = w[b * CIN + i];
    __syncthreads();
    const float* row = aw + (size_t)c * CIN;
    float s = 0.f;
#pragma unroll 4
    for (int k = 0; k < CIN; k++) s += sw[k] * row[k];
    g_styles[b * CIN + c] = s * 0.044194173824159216f + ab[c];
}

// ---------------------------------------------------------------------------
// wsq[co,ci] = sum_k weight[co,ci,k]^2   (exact fp32, for demodulation)
// ---------------------------------------------------------------------------
__global__ void wsq_kernel(const float* __restrict__ weight) {
    int idx = blockIdx.x * 256 + threadIdx.x;
    const float* p = weight + (size_t)idx * 9;
    float s = 0.f;
#pragma unroll
    for (int k = 0; k < 9; k++) { float v = p[k]; s += v * v; }
    g_wsq[idx] = s;
}

// ---------------------------------------------------------------------------
// wt3[cc][tap][co][s] = fp16( weight[co][cc*16 + perm(s)][8-tap] )
// perm: s -> q=s>>1, w=s&1 ; ci_local = q + 7*(q&1) + w
// (pairs interleaved so one LDS.64 yields both k-halves of the B fragment)
// ---------------------------------------------------------------------------
__global__ void wt3_kernel(const float* __restrict__ weight) {
    int idx = blockIdx.x * 256 + threadIdx.x;        // < NCC*9*512*16
    int s   = idx & 15;
    int co  = (idx >> 4) & 511;
    int tap = (idx >> 13) % 9;
    int cc  = idx / (9 * 8192);
    int q = s >> 1, w = s & 1;
    int ci = cc * 16 + q + 7 * (q & 1) + w;
    g_wt3[idx] = __float2half_rn(weight[(size_t)co * (CIN * 9) + ci * 9 + (8 - tap)]);
}

// ---------------------------------------------------------------------------
// dcoef[b,co] = rsqrt(sum_ci wsq[co,ci]*styles[b,ci]^2 + 1e-8)
// ---------------------------------------------------------------------------
__global__ void dcoef_kernel() {
    __shared__ float s2[CIN];
    int b = blockIdx.y;
    int c = blockIdx.x * 128 + threadIdx.x;
    for (int i = threadIdx.x; i < CIN; i += 128) {
        float s = g_styles[b * CIN + i];
        s2[i] = s * s;
    }
    __syncthreads();
    const float* row = g_wsq + (size_t)c * CIN;
    float s = 0.f;
#pragma unroll 4
    for (int k = 0; k < CIN; k++) s += row[k] * s2[k];
    g_dcoef[b * COUT + c] = rsqrtf(s + 1e-8f);
}

// ---------------------------------------------------------------------------
// upfirdn2d up=2 fused with style modulation; processes a ci-PAIR per block,
// writes packed __half2 -> fully vectorized fp16 A source for the conv.
// ---------------------------------------------------------------------------
__global__ void up_kernel(const float* __restrict__ x) {
    __shared__ float sx[2][HIN * HIN];
    int bc2 = blockIdx.x;                       // b*NC2 + c2
    int bc = bc2 * 2;                           // = b*CIN + 2*c2
    const float* xp = x + (size_t)bc * HIN * HIN;
    for (int i = threadIdx.x; i < 2 * HIN * HIN; i += 256)
        sx[i >= HIN * HIN][i & (HIN * HIN - 1)] = xp[i];
    __syncthreads();
    float st0 = g_styles[bc], st1 = g_styles[bc + 1];
    unsigned* op = g_xm2 + (size_t)bc2 * XUS * XUS;
    for (int p = threadIdx.x; p < XUS * XUS; p += 256) {
        int i = p / XUS, j = p % XUS;
        int i0, i1; float wv0, wv1;
        if ((i & 1) == 0) { i0 = (i - 2) >> 1; wv0 = 0.75f; i1 = i >> 1;       wv1 = 0.25f; }
        else              { i0 = (i - 3) >> 1; wv0 = 0.25f; i1 = (i - 1) >> 1; wv1 = 0.75f; }
        if (i0 < 0 || i0 >= HIN) { i0 = 0; wv0 = 0.f; }
        if (i1 < 0 || i1 >= HIN) { i1 = 0; wv1 = 0.f; }
        int j0, j1; float wh0, wh1;
        if ((j & 1) == 0) { j0 = (j - 2) >> 1; wh0 = 0.75f; j1 = j >> 1;       wh1 = 0.25f; }
        else              { j0 = (j - 3) >> 1; wh0 = 0.25f; j1 = (j - 1) >> 1; wh1 = 0.75f; }
        if (j0 < 0 || j0 >= HIN) { j0 = 0; wh0 = 0.f; }
        if (j1 < 0 || j1 >= HIN) { j1 = 0; wh1 = 0.f; }
        float v0 = wv0 * (wh0 * sx[0][i0 * HIN + j0] + wh1 * sx[0][i0 * HIN + j1])
                 + wv1 * (wh0 * sx[0][i1 * HIN + j0] + wh1 * sx[0][i1 * HIN + j1]);
        float v1 = wv0 * (wh0 * sx[1][i0 * HIN + j0] + wh1 * sx[1][i0 * HIN + j1])
                 + wv1 * (wh0 * sx[1][i1 * HIN + j0] + wh1 * sx[1][i1 * HIN + j1]);
        __half2 h = __halves2half2(__float2half_rn(v0 * st0), __float2half_rn(v1 * st1));
        op[p] = *(unsigned*)&h;
    }
}

// ---------------------------------------------------------------------------
// Main conv: implicit GEMM, fp16 mma.sync m16n8k16 (fp32 accum) — 2x MACs
// per HMMA vs tf32 k8 (the legacy-mma issue rate is the binding limit).
// Block: 256 px (16x16) x 128 co, 512 threads = 16 warps (8 M x 2 N).
// K = 512 ci in 32 chunks of 16, x 9 taps. A tile register-prefetched.
// ---------------------------------------------------------------------------
__device__ __forceinline__ void mma_f16(float* d, uint2 alo, uint2 ahi, uint2 bf) {
    asm volatile(
        "mma.sync.aligned.m16n8k16.row.col.f32.f16.f16.f32 "
        "{%0,%1,%2,%3}, {%4,%5,%6,%7}, {%8,%9}, {%0,%1,%2,%3};\n"
        : "+f"(d[0]), "+f"(d[1]), "+f"(d[2]), "+f"(d[3])
        : "r"(alo.x), "r"(ahi.x), "r"(alo.y), "r"(ahi.y),
          "r"(bf.x), "r"(bf.y));
}

__global__ __launch_bounds__(512, 1) void conv_kernel(
    const float* __restrict__ bias, const float* __restrict__ noise,
    const float* __restrict__ nsp, float* __restrict__ out) {
    __shared__ unsigned sA[18 * 18 * 8];    // [r][c][8 ci-pair u32] 10368 B
    __shared__ __align__(16) __half sB[9 * 128 * 16];  // [tap][co][16 slots] 36864 B

    const int t    = threadIdx.x;
    const int lane = t & 31;
    const int wid  = t >> 5;
    const int wm   = wid & 7;              // M-warp: image rows wm*2, wm*2+1
    const int wn   = wid >> 3;             // N-warp: co offset wn*64
    const int g    = lane >> 2;            // 0..7
    const int tg   = lane & 3;             // 0..3

    const int tile_h = blockIdx.x >> 2, tile_w = blockIdx.x & 3;
    const int oh0 = tile_h * 16, ow0 = tile_w * 16;
    const int co0 = blockIdx.y * 128;
    const int b   = blockIdx.z;

    float acc[2][8][4];
#pragma unroll
    for (int mi = 0; mi < 2; mi++)
#pragma unroll
        for (int nt = 0; nt < 8; nt++)
#pragma unroll
            for (int r = 0; r < 4; r++) acc[mi][nt][r] = 0.f;

    const unsigned* xmb = g_xm2 + (size_t)b * NC2 * XUS * XUS;
    const uint4* wt4 = (const uint4*)g_wt3;
    uint4* sB4 = (uint4*)sB;
    const uint2* sA64 = (const uint2*)sA;
    const uint2* sB64 = (const uint2*)sB;

    // A-fill index precompute: 2592 u32 words = 8 pairs x 324 pixels
    int aIdx[6], aOff[6];
#pragma unroll
    for (int j = 0; j < 6; j++) {
        int i = t + j * 512;
        if (i < 2592) {
            int q = i / 324, rc = i - q * 324;
            int r = rc / 18, c = rc - r * 18;
            int c2l = (q >> 1) + 4 * (q & 1);           // ci-pair slot -> c2 offset
            aIdx[j] = rc * 8 + q;                        // smem word index
            aOff[j] = c2l * (XUS * XUS) + (oh0 + r) * XUS + (ow0 + c);
        } else { aIdx[j] = -1; aOff[j] = 0; }
    }

    unsigned pfA[6];
    // prefetch chunk 0
#pragma unroll
    for (int j = 0; j < 6; j++)
        if (aIdx[j] >= 0) pfA[j] = __ldg(xmb + aOff[j]);

    for (int cc = 0; cc < NCC; cc++) {
        __syncthreads();
        // store prefetched A
#pragma unroll
        for (int j = 0; j < 6; j++)
            if (aIdx[j] >= 0) sA[aIdx[j]] = pfA[j];
        // copy B (L2-resident weights): 9*128*16 fp16 = 2304 uint4
        {
            const uint4* src = wt4 + ((size_t)cc * 9 * 512 + co0) * 2;
#pragma unroll
            for (int j = 0; j < 5; j++) {
                int i = t + j * 512;
                if (i < 2304) {
                    int tap = i >> 8, jj = i & 255;
                    sB4[i] = src[(size_t)tap * 1024 + jj];
                }
            }
        }
        __syncthreads();
        // prefetch next chunk's A while MMAs run
        if (cc + 1 < NCC) {
            const unsigned* nb = xmb + (size_t)(cc + 1) * 8 * (XUS * XUS);
#pragma unroll
            for (int j = 0; j < 6; j++)
                if (aIdx[j] >= 0) pfA[j] = __ldg(nb + aOff[j]);
        }

#pragma unroll
        for (int kh = 0; kh < 3; kh++) {
            uint2 aLo[2][3], aHi[2][3];
#pragma unroll
            for (int mi = 0; mi < 2; mi++) {
                int r = wm * 2 + mi + kh;
#pragma unroll
                for (int q = 0; q < 3; q++) {
                    aLo[mi][q] = sA64[(r * 18 + g + q) * 4 + tg];
                    aHi[mi][q] = sA64[(r * 18 + g + 8 + q) * 4 + tg];
                }
            }
#pragma unroll
            for (int kw = 0; kw < 3; kw++) {
                int tap = kh * 3 + kw;
#pragma unroll
                for (int nt = 0; nt < 8; nt++) {
                    uint2 bf = sB64[(tap * 128 + wn * 64 + nt * 8 + g) * 4 + tg];
#pragma unroll
                    for (int mi = 0; mi < 2; mi++)
                        mma_f16(acc[mi][nt], aLo[mi][kw], aHi[mi][kw], bf);
                }
            }
        }
    }

    // Epilogue: *dcoef + noise*strength + bias -> leaky_relu * sqrt(2)
    const float ns = nsp[0];
    float dcv[8][2], bsv[8][2];
#pragma unroll
    for (int nt = 0; nt < 8; nt++) {
        int co = co0 + wn * 64 + nt * 8 + 2 * tg;
        dcv[nt][0] = g_dcoef[b * COUT + co];
        dcv[nt][1] = g_dcoef[b * COUT + co + 1];
        bsv[nt][0] = bias[co];
        bsv[nt][1] = bias[co + 1];
    }
#pragma unroll
    for (int mi = 0; mi < 2; mi++) {
        int oh = oh0 + wm * 2 + mi;
        float nz0 = noise[oh * RES + ow0 + g] * ns;
        float nz1 = noise[oh * RES + ow0 + g + 8] * ns;
#pragma unroll
        for (int nt = 0; nt < 8; nt++) {
            int co = co0 + wn * 64 + nt * 8 + 2 * tg;
            float v0 = acc[mi][nt][0] * dcv[nt][0] + nz0 + bsv[nt][0];
            float v1 = acc[mi][nt][1] * dcv[nt][1] + nz0 + bsv[nt][1];
            float v2 = acc[mi][nt][2] * dcv[nt][0] + nz1 + bsv[nt][0];
            float v3 = acc[mi][nt][3] * dcv[nt][1] + nz1 + bsv[nt][1];
            v0 = ((v0 > 0.f) ? v0 : 0.2f * v0) * 1.4142135623730951f;
            v1 = ((v1 > 0.f) ? v1 : 0.2f * v1) * 1.4142135623730951f;
            v2 = ((v2 > 0.f) ? v2 : 0.2f * v2) * 1.4142135623730951f;
            v3 = ((v3 > 0.f) ? v3 : 0.2f * v3) * 1.4142135623730951f;
            size_t p0 = (((size_t)b * COUT + co) * RES + oh) * RES + ow0;
            size_t p1 = (((size_t)b * COUT + co + 1) * RES + oh) * RES + ow0;
            out[p0 + g]     = v0;
            out[p1 + g]     = v1;
            out[p0 + g + 8] = v2;
            out[p1 + g + 8] = v3;
        }
    }
}

// ---------------------------------------------------------------------------
extern "C" void kernel_launch(void* const* d_in, const int* in_sizes, int n_in,
                              void* d_out, int out_size) {
    const float* x      = (const float*)d_in[0];
    const float* w      = (const float*)d_in[1];
    const float* aw     = (const float*)d_in[2];
    const float* ab     = (const float*)d_in[3];
    const float* weight = (const float*)d_in[4];
    const float* bias   = (const float*)d_in[5];
    const float* noise  = (const float*)d_in[6];
    const float* nstr   = (const float*)d_in[7];
    float* out = (float*)d_out;

    styles_kernel<<<dim3(4, NB), 128>>>(w, aw, ab);
    wsq_kernel<<<COUT * CIN / 256, 256>>>(weight);
    wt3_kernel<<<NCC * 9 * COUT * 16 / 256, 256>>>(weight);
    dcoef_kernel<<<dim3(4, NB), 128>>>();
    up_kernel<<<NB * NC2, 256>>>(x);
    conv_kernel<<<dim3(16, 4, NB), 512>>>(bias, noise, nstr, out);
}

// round 11
// speedup vs baseline: 5.0543x; 1.0019x over previous
#include <cuda_runtime.h>
#include <cuda_fp16.h>
#include <cstdint>

#define NB   16
#define CIN  512
#define COUT 512
#define HIN  32
#define XUS  66
#define RES  64
#define NC2  (CIN / 2)          // 256 ci-pairs
#define NCC  32                 // ci chunks of 16

// Scratch (device globals — no allocation allowed)
__device__ float g_styles[NB * CIN];
__device__ float g_dcoef[NB * COUT];
__device__ float g_wsq[COUT * CIN];
// wt3[cc][tap][co][slot]: fp16, slot s -> ci = cc*16 + perm(s)  (3x3 flipped)
__device__ __half g_wt3[NCC * 9 * COUT * 16];
// xm2[b][c2][pix]: __half2 of ci-pair (2*c2, 2*c2+1), modulated+upsampled
__device__ unsigned g_xm2[(size_t)NB * NC2 * XUS * XUS];

// ---------------------------------------------------------------------------
// styles[b,c] = dot(w[b,:], affine_weight[c,:]) / sqrt(512) + affine_bias[c]
// ---------------------------------------------------------------------------
__global__ void styles_kernel(const float* __restrict__ w,
                              const float* __restrict__ aw,
                              const float* __restrict__ ab) {
    __shared__ float sw[CIN];
    int b = blockIdx.y;
    int c = blockIdx.x * 128 + threadIdx.x;
    for (int i = threadIdx.x; i < CIN; i += 128) sw[i] = w[b * CIN + i];
    __syncthreads();
    const float* row = aw + (size_t)c * CIN;
    float s = 0.f;
#pragma unroll 4
    for (int k = 0; k < CIN; k++) s += sw[k] * row[k];
    g_styles[b * CIN + c] = s * 0.044194173824159216f + ab[c];
}

// ---------------------------------------------------------------------------
// wsq[co,ci] = sum_k weight[co,ci,k]^2   (exact fp32, for demodulation)
// ---------------------------------------------------------------------------
__global__ void wsq_kernel(const float* __restrict__ weight) {
    int idx = blockIdx.x * 256 + threadIdx.x;
    const float* p = weight + (size_t)idx * 9;
    float s = 0.f;
#pragma unroll
    for (int k = 0; k < 9; k++) { float v = p[k]; s += v * v; }
    g_wsq[idx] = s;
}

// ---------------------------------------------------------------------------
// wt3[cc][tap][co][s] = fp16( weight[co][cc*16 + perm(s)][8-tap] )
// perm: s -> q=s>>1, w=s&1 ; ci_local = q + 7*(q&1) + w
// (pairs interleaved so one LDS.64 yields both k-halves of the B fragment)
// ---------------------------------------------------------------------------
__global__ void wt3_kernel(const float* __restrict__ weight) {
    int idx = blockIdx.x * 256 + threadIdx.x;        // < NCC*9*512*16
    int s   = idx & 15;
    int co  = (idx >> 4) & 511;
    int tap = (idx >> 13) % 9;
    int cc  = idx / (9 * 8192);
    int q = s >> 1, w = s & 1;
    int ci = cc * 16 + q + 7 * (q & 1) + w;
    g_wt3[idx] = __float2half_rn(weight[(size_t)co * (CIN * 9) + ci * 9 + (8 - tap)]);
}

// ---------------------------------------------------------------------------
// dcoef[b,co] = rsqrt(sum_ci wsq[co,ci]*styles[b,ci]^2 + 1e-8)
// ---------------------------------------------------------------------------
__global__ void dcoef_kernel() {
    __shared__ float s2[CIN];
    int b = blockIdx.y;
    int c = blockIdx.x * 128 + threadIdx.x;
    for (int i = threadIdx.x; i < CIN; i += 128) {
        float s = g_styles[b * CIN + i];
        s2[i] = s * s;
    }
    __syncthreads();
    const float* row = g_wsq + (size_t)c * CIN;
    float s = 0.f;
#pragma unroll 4
    for (int k = 0; k < CIN; k++) s += row[k] * s2[k];
    g_dcoef[b * COUT + c] = rsqrtf(s + 1e-8f);
}

// ---------------------------------------------------------------------------
// upfirdn2d up=2 fused with style modulation; processes a ci-PAIR per block,
// writes packed __half2 -> fully vectorized fp16 A source for the conv.
// ---------------------------------------------------------------------------
__global__ void up_kernel(const float* __restrict__ x) {
    __shared__ float sx[2][HIN * HIN];
    int bc2 = blockIdx.x;                       // b*NC2 + c2
    int bc = bc2 * 2;                           // = b*CIN + 2*c2
    const float* xp = x + (size_t)bc * HIN * HIN;
    for (int i = threadIdx.x; i < 2 * HIN * HIN; i += 256)
        sx[i >= HIN * HIN][i & (HIN * HIN - 1)] = xp[i];
    __syncthreads();
    float st0 = g_styles[bc], st1 = g_styles[bc + 1];
    unsigned* op = g_xm2 + (size_t)bc2 * XUS * XUS;
    for (int p = threadIdx.x; p < XUS * XUS; p += 256) {
        int i = p / XUS, j = p % XUS;
        int i0, i1; float wv0, wv1;
        if ((i & 1) == 0) { i0 = (i - 2) >> 1; wv0 = 0.75f; i1 = i >> 1;       wv1 = 0.25f; }
        else              { i0 = (i - 3) >> 1; wv0 = 0.25f; i1 = (i - 1) >> 1; wv1 = 0.75f; }
        if (i0 < 0 || i0 >= HIN) { i0 = 0; wv0 = 0.f; }
        if (i1 < 0 || i1 >= HIN) { i1 = 0; wv1 = 0.f; }
        int j0, j1; float wh0, wh1;
        if ((j & 1) == 0) { j0 = (j - 2) >> 1; wh0 = 0.75f; j1 = j >> 1;       wh1 = 0.25f; }
        else              { j0 = (j - 3) >> 1; wh0 = 0.25f; j1 = (j - 1) >> 1; wh1 = 0.75f; }
        if (j0 < 0 || j0 >= HIN) { j0 = 0; wh0 = 0.f; }
        if (j1 < 0 || j1 >= HIN) { j1 = 0; wh1 = 0.f; }
        float v0 = wv0 * (wh0 * sx[0][i0 * HIN + j0] + wh1 * sx[0][i0 * HIN + j1])
                 + wv1 * (wh0 * sx[0][i1 * HIN + j0] + wh1 * sx[0][i1 * HIN + j1]);
        float v1 = wv0 * (wh0 * sx[1][i0 * HIN + j0] + wh1 * sx[1][i0 * HIN + j1])
                 + wv1 * (wh0 * sx[1][i1 * HIN + j0] + wh1 * sx[1][i1 * HIN + j1]);
        __half2 h = __halves2half2(__float2half_rn(v0 * st0), __float2half_rn(v1 * st1));
        op[p] = *(unsigned*)&h;
    }
}

// ---------------------------------------------------------------------------
// Main conv: implicit GEMM, fp16 mma.sync m16n8k16 (fp32 accum) — 2x MACs
// per HMMA vs tf32 k8 (the legacy-mma issue rate is the binding limit).
// Block: 256 px (16x16) x 128 co, 512 threads = 16 warps (8 M x 2 N).
// K = 512 ci in 32 chunks of 16, x 9 taps. A tile register-prefetched.
// ---------------------------------------------------------------------------
__device__ __forceinline__ void mma_f16(float* d, uint2 alo, uint2 ahi, uint2 bf) {
    asm volatile(
        "mma.sync.aligned.m16n8k16.row.col.f32.f16.f16.f32 "
        "{%0,%1,%2,%3}, {%4,%5,%6,%7}, {%8,%9}, {%0,%1,%2,%3};\n"
        : "+f"(d[0]), "+f"(d[1]), "+f"(d[2]), "+f"(d[3])
        : "r"(alo.x), "r"(ahi.x), "r"(alo.y), "r"(ahi.y),
          "r"(bf.x), "r"(bf.y));
}

__global__ __launch_bounds__(512, 1) void conv_kernel(
    const float* __restrict__ bias, const float* __restrict__ noise,
    const float* __restrict__ nsp, float* __restrict__ out) {
    __shared__ unsigned sA[18 * 18 * 8];    // [r][c][8 ci-pair u32] 10368 B
    __shared__ __align__(16) __half sB[9 * 128 * 16];  // [tap][co][16 slots] 36864 B

    const int t    = threadIdx.x;
    const int lane = t & 31;
    const int wid  = t >> 5;
    const int wm   = wid & 7;              // M-warp: image rows wm*2, wm*2+1
    const int wn   = wid >> 3;             // N-warp: co offset wn*64
    const int g    = lane >> 2;            // 0..7
    const int tg   = lane & 3;             // 0..3

    const int tile_h = blockIdx.x >> 2, tile_w = blockIdx.x & 3;
    const int oh0 = tile_h * 16, ow0 = tile_w * 16;
    const int co0 = blockIdx.y * 128;
    const int b   = blockIdx.z;

    float acc[2][8][4];
#pragma unroll
    for (int mi = 0; mi < 2; mi++)
#pragma unroll
        for (int nt = 0; nt < 8; nt++)
#pragma unroll
            for (int r = 0; r < 4; r++) acc[mi][nt][r] = 0.f;

    const unsigned* xmb = g_xm2 + (size_t)b * NC2 * XUS * XUS;
    const uint4* wt4 = (const uint4*)g_wt3;
    uint4* sB4 = (uint4*)sB;
    const uint2* sA64 = (const uint2*)sA;
    const uint2* sB64 = (const uint2*)sB;

    // A-fill index precompute: 2592 u32 words = 8 pairs x 324 pixels
    int aIdx[6], aOff[6];
#pragma unroll
    for (int j = 0; j < 6; j++) {
        int i = t + j * 512;
        if (i < 2592) {
            int q = i / 324, rc = i - q * 324;
            int r = rc / 18, c = rc - r * 18;
            int c2l = (q >> 1) + 4 * (q & 1);           // ci-pair slot -> c2 offset
            aIdx[j] = rc * 8 + q;                        // smem word index
            aOff[j] = c2l * (XUS * XUS) + (oh0 + r) * XUS + (ow0 + c);
        } else { aIdx[j] = -1; aOff[j] = 0; }
    }

    unsigned pfA[6];
    // prefetch chunk 0
#pragma unroll
    for (int j = 0; j < 6; j++)
        if (aIdx[j] >= 0) pfA[j] = __ldg(xmb + aOff[j]);

    for (int cc = 0; cc < NCC; cc++) {
        __syncthreads();
        // store prefetched A
#pragma unroll
        for (int j = 0; j < 6; j++)
            if (aIdx[j] >= 0) sA[aIdx[j]] = pfA[j];
        // copy B (L2-resident weights): 9*128*16 fp16 = 2304 uint4
        {
            const uint4* src = wt4 + ((size_t)cc * 9 * 512 + co0) * 2;
#pragma unroll
            for (int j = 0; j < 5; j++) {
                int i = t + j * 512;
                if (i < 2304) {
                    int tap = i >> 8, jj = i & 255;
                    sB4[i] = src[(size_t)tap * 1024 + jj];
                }
            }
        }
        __syncthreads();
        // prefetch next chunk's A while MMAs run
        if (cc + 1 < NCC) {
            const unsigned* nb = xmb + (size_t)(cc + 1) * 8 * (XUS * XUS);
#pragma unroll
            for (int j = 0; j < 6; j++)
                if (aIdx[j] >= 0) pfA[j] = __ldg(nb + aOff[j]);
        }

#pragma unroll
        for (int kh = 0; kh < 3; kh++) {
            uint2 aLo[2][3], aHi[2][3];
#pragma unroll
            for (int mi = 0; mi < 2; mi++) {
                int r = wm * 2 + mi + kh;
#pragma unroll
                for (int q = 0; q < 3; q++) {
                    aLo[mi][q] = sA64[(r * 18 + g + q) * 4 + tg];
                    aHi[mi][q] = sA64[(r * 18 + g + 8 + q) * 4 + tg];
                }
            }
#pragma unroll
            for (int kw = 0; kw < 3; kw++) {
                int tap = kh * 3 + kw;
#pragma unroll
                for (int nt = 0; nt < 8; nt++) {
                    uint2 bf = sB64[(tap * 128 + wn * 64 + nt * 8 + g) * 4 + tg];
#pragma unroll
                    for (int mi = 0; mi < 2; mi++)
                        mma_f16(acc[mi][nt], aLo[mi][kw], aHi[mi][kw], bf);
                }
            }
        }
    }

    // Epilogue: *dcoef + noise*strength + bias -> leaky_relu * sqrt(2)
    const float ns = nsp[0];
    float dcv[8][2], bsv[8][2];
#pragma unroll
    for (int nt = 0; nt < 8; nt++) {
        int co = co0 + wn * 64 + nt * 8 + 2 * tg;
        dcv[nt][0] = g_dcoef[b * COUT + co];
        dcv[nt][1] = g_dcoef[b * COUT + co + 1];
        bsv[nt][0] = bias[co];
        bsv[nt][1] = bias[co + 1];
    }
#pragma unroll
    for (int mi = 0; mi < 2; mi++) {
        int oh = oh0 + wm * 2 + mi;
        float nz0 = noise[oh * RES + ow0 + g] * ns;
        float nz1 = noise[oh * RES + ow0 + g + 8] * ns;
#pragma unroll
        for (int nt = 0; nt < 8; nt++) {
            int co = co0 + wn * 64 + nt * 8 + 2 * tg;
            float v0 = acc[mi][nt][0] * dcv[nt][0] + nz0 + bsv[nt][0];
            float v1 = acc[mi][nt][1] * dcv[nt][1] + nz0 + bsv[nt][1];
            float v2 = acc[mi][nt][2] * dcv[nt][0] + nz1 + bsv[nt][0];
            float v3 = acc[mi][nt][3] * dcv[nt][1] + nz1 + bsv[nt][1];
            v0 = ((v0 > 0.f) ? v0 : 0.2f * v0) * 1.4142135623730951f;
            v1 = ((v1 > 0.f) ? v1 : 0.2f * v1) * 1.4142135623730951f;
            v2 = ((v2 > 0.f) ? v2 : 0.2f * v2) * 1.4142135623730951f;
            v3 = ((v3 > 0.f) ? v3 : 0.2f * v3) * 1.4142135623730951f;
            size_t p0 = (((size_t)b * COUT + co) * RES + oh) * RES + ow0;
            size_t p1 = (((size_t)b * COUT + co + 1) * RES + oh) * RES + ow0;
            out[p0 + g]     = v0;
            out[p1 + g]     = v1;
            out[p0 + g + 8] = v2;
            out[p1 + g + 8] = v3;
        }
    }
}

// ---------------------------------------------------------------------------
extern "C" void kernel_launch(void* const* d_in, const int* in_sizes, int n_in,
                              void* d_out, int out_size) {
    const float* x      = (const float*)d_in[0];
    const float* w      = (const float*)d_in[1];
    const float* aw     = (const float*)d_in[2];
    const float* ab     = (const float*)d_in[3];
    const float* weight = (const float*)d_in[4];
    const float* bias   = (const float*)d_in[5];
    const float* noise  = (const float*)d_in[6];
    const float* nstr   = (const float*)d_in[7];
    float* out = (float*)d_out;

    styles_kernel<<<dim3(4, NB), 128>>>(w, aw, ab);
    wsq_kernel<<<COUT * CIN / 256, 256>>>(weight);
    wt3_kernel<<<NCC * 9 * COUT * 16 / 256, 256>>>(weight);
    dcoef_kernel<<<dim3(4, NB), 128>>>();
    up_kernel<<<NB * NC2, 256>>>(x);
    conv_kernel<<<dim3(16, 4, NB), 512>>>(bias, noise, nstr, out);
}

// round 16
// speedup vs baseline: 5.8070x; 1.1489x over previous
#include <cuda_runtime.h>
#include <cuda_fp16.h>
#include <cstdint>

#define NB   16
#define CIN  512
#define COUT 512
#define HIN  32
#define XUS  66
#define RES  64
#define NC2  (CIN / 2)          // 256 ci-pairs
#define NCC  32                 // ci chunks of 16

// conv dynamic smem: A 2 x 10368B, B 2 x 36864B
#define SMA_SZ 10368
#define SMB_SZ 36864
#define SMB_OFF (2 * SMA_SZ)            // 20736
#define CONV_SMEM (SMB_OFF + 2 * SMB_SZ)  // 94464

// Scratch (device globals — no allocation allowed)
__device__ float g_styles[NB * CIN];
__device__ float g_dcoef[NB * COUT];
__device__ float g_wsq[COUT * CIN];
// wt3[cc][tap][co][slot]: fp16, slot s -> ci = cc*16 + perm(s)  (3x3 flipped)
__device__ __half g_wt3[NCC * 9 * COUT * 16];
// xm2[b][c2][pix]: __half2 of ci-pair (2*c2, 2*c2+1), modulated+upsampled
__device__ unsigned g_xm2[(size_t)NB * NC2 * XUS * XUS];

// ---------------------------------------------------------------------------
__device__ __forceinline__ uint32_t smem_u32(const void* p) {
    uint32_t a;
    asm("{ .reg .u64 t; cvta.to.shared.u64 t, %1; cvt.u32.u64 %0, t; }" : "=r"(a) : "l"(p));
    return a;
}
__device__ __forceinline__ void cpa4(uint32_t dst, const void* src) {
    asm volatile("cp.async.ca.shared.global [%0], [%1], 4;" :: "r"(dst), "l"(src) : "memory");
}
__device__ __forceinline__ void cpa16(uint32_t dst, const void* src) {
    asm volatile("cp.async.cg.shared.global [%0], [%1], 16;" :: "r"(dst), "l"(src) : "memory");
}
__device__ __forceinline__ void cpa_commit() {
    asm volatile("cp.async.commit_group;" ::: "memory");
}
template <int N>
__device__ __forceinline__ void cpa_wait() {
    asm volatile("cp.async.wait_group %0;" :: "n"(N) : "memory");
}
__device__ __forceinline__ float warp_sum(float s) {
#pragma unroll
    for (int m = 16; m > 0; m >>= 1) s += __shfl_xor_sync(0xffffffffu, s, m);
    return s;
}

// ---------------------------------------------------------------------------
// styles[b,c] = dot(w[b,:], affine_weight[c,:]) / sqrt(512) + affine_bias[c]
// warp-per-output: block 256 thr = 8 warps = 8 outputs; grid (64, NB)
// ---------------------------------------------------------------------------
__global__ void styles_kernel(const float* __restrict__ w,
                              const float* __restrict__ aw,
                              const float* __restrict__ ab) {
    __shared__ float sw[CIN];
    int b = blockIdx.y;
    int lane = threadIdx.x & 31, wid = threadIdx.x >> 5;
    int c = blockIdx.x * 8 + wid;
    for (int i = threadIdx.x; i < CIN; i += 256) sw[i] = w[b * CIN + i];
    __syncthreads();
    const float4* row = (const float4*)(aw + (size_t)c * CIN);
    float s = 0.f;
#pragma unroll
    for (int i = 0; i < 4; i++) {
        int k4 = i * 32 + lane;
        float4 v = row[k4];
        s += v.x * sw[4 * k4] + v.y * sw[4 * k4 + 1] + v.z * sw[4 * k4 + 2] + v.w * sw[4 * k4 + 3];
    }
    s = warp_sum(s);
    if (lane == 0) g_styles[b * CIN + c] = s * 0.044194173824159216f + ab[c];
}

// ---------------------------------------------------------------------------
// wsq[co,ci] = sum_k weight[co,ci,k]^2
// ---------------------------------------------------------------------------
__global__ void wsq_kernel(const float* __restrict__ weight) {
    int idx = blockIdx.x * 256 + threadIdx.x;
    const float* p = weight + (size_t)idx * 9;
    float s = 0.f;
#pragma unroll
    for (int k = 0; k < 9; k++) { float v = p[k]; s += v * v; }
    g_wsq[idx] = s;
}

// ---------------------------------------------------------------------------
// wt3[cc][tap][co][s] = fp16( weight[co][cc*16 + perm(s)][8-tap] )
// perm: s -> q=s>>1, w=s&1 ; ci_local = q + 7*(q&1) + w
// ---------------------------------------------------------------------------
__global__ void wt3_kernel(const float* __restrict__ weight) {
    int idx = blockIdx.x * 256 + threadIdx.x;        // < NCC*9*512*16
    int s   = idx & 15;
    int co  = (idx >> 4) & 511;
    int tap = (idx >> 13) % 9;
    int cc  = idx / (9 * 8192);
    int q = s >> 1, w = s & 1;
    int ci = cc * 16 + q + 7 * (q & 1) + w;
    g_wt3[idx] = __float2half_rn(weight[(size_t)co * (CIN * 9) + ci * 9 + (8 - tap)]);
}

// ---------------------------------------------------------------------------
// dcoef[b,co] = rsqrt(sum_ci wsq[co,ci]*styles[b,ci]^2 + 1e-8)
// warp-per-output, same shape as styles_kernel
// ---------------------------------------------------------------------------
__global__ void dcoef_kernel() {
    __shared__ float s2[CIN];
    int b = blockIdx.y;
    int lane = threadIdx.x & 31, wid = threadIdx.x >> 5;
    int c = blockIdx.x * 8 + wid;
    for (int i = threadIdx.x; i < CIN; i += 256) {
        float s = g_styles[b * CIN + i];
        s2[i] = s * s;
    }
    __syncthreads();
    const float4* row = (const float4*)(g_wsq + (size_t)c * CIN);
    float s = 0.f;
#pragma unroll
    for (int i = 0; i < 4; i++) {
        int k4 = i * 32 + lane;
        float4 v = row[k4];
        s += v.x * s2[4 * k4] + v.y * s2[4 * k4 + 1] + v.z * s2[4 * k4 + 2] + v.w * s2[4 * k4 + 3];
    }
    s = warp_sum(s);
    if (lane == 0) g_dcoef[b * COUT + c] = rsqrtf(s + 1e-8f);
}

// ---------------------------------------------------------------------------
// upfirdn2d up=2 fused with style modulation; ci-pair per block, __half2 out
// ---------------------------------------------------------------------------
__global__ void up_kernel(const float* __restrict__ x) {
    __shared__ float sx[2][HIN * HIN];
    int bc2 = blockIdx.x;
    int bc = bc2 * 2;
    const float* xp = x + (size_t)bc * HIN * HIN;
    for (int i = threadIdx.x; i < 2 * HIN * HIN; i += 256)
        sx[i >= HIN * HIN][i & (HIN * HIN - 1)] = xp[i];
    __syncthreads();
    float st0 = g_styles[bc], st1 = g_styles[bc + 1];
    unsigned* op = g_xm2 + (size_t)bc2 * XUS * XUS;
    for (int p = threadIdx.x; p < XUS * XUS; p += 256) {
        int i = p / XUS, j = p % XUS;
        int i0, i1; float wv0, wv1;
        if ((i & 1) == 0) { i0 = (i - 2) >> 1; wv0 = 0.75f; i1 = i >> 1;       wv1 = 0.25f; }
        else              { i0 = (i - 3) >> 1; wv0 = 0.25f; i1 = (i - 1) >> 1; wv1 = 0.75f; }
        if (i0 < 0 || i0 >= HIN) { i0 = 0; wv0 = 0.f; }
        if (i1 < 0 || i1 >= HIN) { i1 = 0; wv1 = 0.f; }
        int j0, j1; float wh0, wh1;
        if ((j & 1) == 0) { j0 = (j - 2) >> 1; wh0 = 0.75f; j1 = j >> 1;       wh1 = 0.25f; }
        else              { j0 = (j - 3) >> 1; wh0 = 0.25f; j1 = (j - 1) >> 1; wh1 = 0.75f; }
        if (j0 < 0 || j0 >= HIN) { j0 = 0; wh0 = 0.f; }
        if (j1 < 0 || j1 >= HIN) { j1 = 0; wh1 = 0.f; }
        float v0 = wv0 * (wh0 * sx[0][i0 * HIN + j0] + wh1 * sx[0][i0 * HIN + j1])
                 + wv1 * (wh0 * sx[0][i1 * HIN + j0] + wh1 * sx[0][i1 * HIN + j1]);
        float v1 = wv0 * (wh0 * sx[1][i0 * HIN + j0] + wh1 * sx[1][i0 * HIN + j1])
                 + wv1 * (wh0 * sx[1][i1 * HIN + j0] + wh1 * sx[1][i1 * HIN + j1]);
        __half2 h = __halves2half2(__float2half_rn(v0 * st0), __float2half_rn(v1 * st1));
        op[p] = *(unsigned*)&h;
    }
}

// ---------------------------------------------------------------------------
// Main conv: implicit GEMM, fp16 mma.sync m16n8k16 (fp32 accum).
// Block: 256 px (16x16) x 128 co, 512 threads = 16 warps (8 M x 2 N).
// K = 512 ci in 32 chunks of 16, x 9 taps.
// cp.async 2-stage double buffer for BOTH A patch and B weights: removes the
// exposed per-chunk L2 latency of the old synchronous LDG->STS fills.
// ---------------------------------------------------------------------------
__device__ __forceinline__ void mma_f16(float* d, uint2 alo, uint2 ahi, uint2 bf) {
    asm volatile(
        "mma.sync.aligned.m16n8k16.row.col.f32.f16.f16.f32 "
        "{%0,%1,%2,%3}, {%4,%5,%6,%7}, {%8,%9}, {%0,%1,%2,%3};\n"
        : "+f"(d[0]), "+f"(d[1]), "+f"(d[2]), "+f"(d[3])
        : "r"(alo.x), "r"(ahi.x), "r"(alo.y), "r"(ahi.y),
          "r"(bf.x), "r"(bf.y));
}

__global__ __launch_bounds__(512, 1) void conv_kernel(
    const float* __restrict__ bias, const float* __restrict__ noise,
    const float* __restrict__ nsp, float* __restrict__ out) {
    extern __shared__ char smem[];
    const uint32_t sbase = smem_u32(smem);

    const int t    = threadIdx.x;
    const int lane = t & 31;
    const int wid  = t >> 5;
    const int wm   = wid & 7;              // M-warp: image rows wm*2, wm*2+1
    const int wn   = wid >> 3;             // N-warp: co offset wn*64
    const int g    = lane >> 2;            // 0..7
    const int tg   = lane & 3;             // 0..3

    const int tile_h = blockIdx.x >> 2, tile_w = blockIdx.x & 3;
    const int oh0 = tile_h * 16, ow0 = tile_w * 16;
    const int co0 = blockIdx.y * 128;
    const int b   = blockIdx.z;

    float acc[2][8][4];
#pragma unroll
    for (int mi = 0; mi < 2; mi++)
#pragma unroll
        for (int nt = 0; nt < 8; nt++)
#pragma unroll
            for (int r = 0; r < 4; r++) acc[mi][nt][r] = 0.f;

    const unsigned* xmb = g_xm2 + (size_t)b * NC2 * XUS * XUS;
    const uint4* wt4 = (const uint4*)g_wt3;

    // A-fill index precompute: 2592 u32 words = 8 pairs x 324 pixels
    int aIdx[6], aOff[6];
#pragma unroll
    for (int j = 0; j < 6; j++) {
        int i = t + j * 512;
        if (i < 2592) {
            int q = i / 324, rc = i - q * 324;
            int r = rc / 18, c = rc - r * 18;
            int c2l = (q >> 1) + 4 * (q & 1);           // ci-pair slot -> c2 offset
            aIdx[j] = rc * 8 + q;                        // smem word index
            aOff[j] = c2l * (XUS * XUS) + (oh0 + r) * XUS + (ow0 + c);
        } else { aIdx[j] = -1; aOff[j] = 0; }
    }

    // ---- async fill of one chunk into one stage ----
    auto issue = [&](int cc, int st) {
        const unsigned* abase = xmb + (size_t)cc * 8 * (XUS * XUS);
        uint32_t dA = sbase + st * SMA_SZ;
#pragma unroll
        for (int j = 0; j < 6; j++)
            if (aIdx[j] >= 0) cpa4(dA + aIdx[j] * 4, abase + aOff[j]);
        const uint4* src = wt4 + ((size_t)cc * 9 * 512 + co0) * 2;
        uint32_t dB = sbase + SMB_OFF + st * SMB_SZ;
#pragma unroll
        for (int j = 0; j < 5; j++) {
            int i = t + j * 512;
            if (i < 2304) {
                int tap = i >> 8, jj = i & 255;
                cpa16(dB + i * 16, src + (size_t)tap * 1024 + jj);
            }
        }
        cpa_commit();
    };

    issue(0, 0);

    for (int cc = 0; cc < NCC; cc++) {
        const int st = cc & 1;
        if (cc + 1 < NCC) {
            issue(cc + 1, st ^ 1);
            cpa_wait<1>();
        } else {
            cpa_wait<0>();
        }
        __syncthreads();

        const uint2* sA64 = (const uint2*)(smem + st * SMA_SZ);
        const uint2* sB64 = (const uint2*)(smem + SMB_OFF + st * SMB_SZ);
#pragma unroll
        for (int kh = 0; kh < 3; kh++) {
            uint2 aLo[2][3], aHi[2][3];
#pragma unroll
            for (int mi = 0; mi < 2; mi++) {
                int r = wm * 2 + mi + kh;
#pragma unroll
                for (int q = 0; q < 3; q++) {
                    aLo[mi][q] = sA64[(r * 18 + g + q) * 4 + tg];
                    aHi[mi][q] = sA64[(r * 18 + g + 8 + q) * 4 + tg];
                }
            }
#pragma unroll
            for (int kw = 0; kw < 3; kw++) {
                int tap = kh * 3 + kw;
#pragma unroll
                for (int nt = 0; nt < 8; nt++) {
                    uint2 bf = sB64[(tap * 128 + wn * 64 + nt * 8 + g) * 4 + tg];
#pragma unroll
                    for (int mi = 0; mi < 2; mi++)
                        mma_f16(acc[mi][nt], aLo[mi][kw], aHi[mi][kw], bf);
                }
            }
        }
        __syncthreads();   // guard stage reuse before next cp.async overwrite
    }

    // Epilogue: *dcoef + noise*strength + bias -> leaky_relu * sqrt(2)
    const float ns = nsp[0];
    float dcv[8][2], bsv[8][2];
#pragma unroll
    for (int nt = 0; nt < 8; nt++) {
        int co = co0 + wn * 64 + nt * 8 + 2 * tg;
        dcv[nt][0] = g_dcoef[b * COUT + co];
        dcv[nt][1] = g_dcoef[b * COUT + co + 1];
        bsv[nt][0] = bias[co];
        bsv[nt][1] = bias[co + 1];
    }
#pragma unroll
    for (int mi = 0; mi < 2; mi++) {
        int oh = oh0 + wm * 2 + mi;
        float nz0 = noise[oh * RES + ow0 + g] * ns;
        float nz1 = noise[oh * RES + ow0 + g + 8] * ns;
#pragma unroll
        for (int nt = 0; nt < 8; nt++) {
            int co = co0 + wn * 64 + nt * 8 + 2 * tg;
            float v0 = acc[mi][nt][0] * dcv[nt][0] + nz0 + bsv[nt][0];
            float v1 = acc[mi][nt][1] * dcv[nt][1] + nz0 + bsv[nt][1];
            float v2 = acc[mi][nt][2] * dcv[nt][0] + nz1 + bsv[nt][0];
            float v3 = acc[mi][nt][3] * dcv[nt][1] + nz1 + bsv[nt][1];
            v0 = ((v0 > 0.f) ? v0 : 0.2f * v0) * 1.4142135623730951f;
            v1 = ((v1 > 0.f) ? v1 : 0.2f * v1) * 1.4142135623730951f;
            v2 = ((v2 > 0.f) ? v2 : 0.2f * v2) * 1.4142135623730951f;
            v3 = ((v3 > 0.f) ? v3 : 0.2f * v3) * 1.4142135623730951f;
            size_t p0 = (((size_t)b * COUT + co) * RES + oh) * RES + ow0;
            size_t p1 = (((size_t)b * COUT + co + 1) * RES + oh) * RES + ow0;
            out[p0 + g]     = v0;
            out[p1 + g]     = v1;
            out[p0 + g + 8] = v2;
            out[p1 + g + 8] = v3;
        }
    }
}

// ---------------------------------------------------------------------------
extern "C" void kernel_launch(void* const* d_in, const int* in_sizes, int n_in,
                              void* d_out, int out_size) {
    const float* x      = (const float*)d_in[0];
    const float* w      = (const float*)d_in[1];
    const float* aw     = (const float*)d_in[2];
    const float* ab     = (const float*)d_in[3];
    const float* weight = (const float*)d_in[4];
    const float* bias   = (const float*)d_in[5];
    const float* noise  = (const float*)d_in[6];
    const float* nstr   = (const float*)d_in[7];
    float* out = (float*)d_out;

    cudaFuncSetAttribute(conv_kernel, cudaFuncAttributeMaxDynamicSharedMemorySize, CONV_SMEM);

    styles_kernel<<<dim3(64, NB), 256>>>(w, aw, ab);
    wsq_kernel<<<COUT * CIN / 256, 256>>>(weight);
    wt3_kernel<<<NCC * 9 * COUT * 16 / 256, 256>>>(weight);
    dcoef_kernel<<<dim3(64, NB), 256>>>();
    up_kernel<<<NB * NC2, 256>>>(x);
    conv_kernel<<<dim3(16, 4, NB), 512, CONV_SMEM>>>(bias, noise, nstr, out);
}